// round 3
// baseline (speedup 1.0000x reference)
#include <cuda_runtime.h>

#define BB 4
#define DD 128
#define KK 512
#define ALPHA 0.2f
#define OMALPHA 0.8f

__device__ float g_L[BB * KK * DD];   // [b][k][e]  left (incl bias)
__device__ float g_R[BB * DD * KK];   // [b][e][k]  right, d-major
__device__ float g_XT[BB * KK * DD];  // [b][k][d]  xt
__device__ float g_sL[BB * KK];
__device__ float g_sR[BB * KK];

// ---------------- Kernel 1: L,R GEMMs + sL,sR + XT transpose ----------------
__global__ __launch_bounds__(256) void k1(const float* __restrict__ x,
                                          const float* __restrict__ lw,
                                          const float* __restrict__ lb,
                                          const float* __restrict__ a) {
    __shared__ float sx[128 * 17];  // [d][k] pad 17
    __shared__ float ssL[16], ssR[16];
    const int tid = threadIdx.x;
    const int b = blockIdx.x >> 5;
    const int k0 = (blockIdx.x & 31) << 4;

    for (int idx = tid; idx < 2048; idx += 256) {
        int d = idx >> 4, k = idx & 15;
        sx[d * 17 + k] = x[(b * DD + d) * KK + k0 + k];
    }
    if (tid < 16) { ssL[tid] = 0.f; ssR[tid] = 0.f; }
    __syncthreads();

    const int eg = tid & 31, kg = tid >> 5;
    const int e0 = eg * 4, kq = kg * 2;
    float aL0[4] = {0,0,0,0}, aL1[4] = {0,0,0,0};
    float aR0[4] = {0,0,0,0}, aR1[4] = {0,0,0,0};

#pragma unroll 4
    for (int d = 0; d < 128; d++) {
        float x0 = sx[d * 17 + kq];
        float x1 = sx[d * 17 + kq + 1];
        float4 w1 = *(const float4*)&lw[d * 128 + e0];
        float4 w2 = *(const float4*)&lw[(128 + d) * 128 + e0];
        aL0[0] = fmaf(x0, w1.x, aL0[0]); aL0[1] = fmaf(x0, w1.y, aL0[1]);
        aL0[2] = fmaf(x0, w1.z, aL0[2]); aL0[3] = fmaf(x0, w1.w, aL0[3]);
        aL1[0] = fmaf(x1, w1.x, aL1[0]); aL1[1] = fmaf(x1, w1.y, aL1[1]);
        aL1[2] = fmaf(x1, w1.z, aL1[2]); aL1[3] = fmaf(x1, w1.w, aL1[3]);
        aR0[0] = fmaf(x0, w2.x, aR0[0]); aR0[1] = fmaf(x0, w2.y, aR0[1]);
        aR0[2] = fmaf(x0, w2.z, aR0[2]); aR0[3] = fmaf(x0, w2.w, aR0[3]);
        aR1[0] = fmaf(x1, w2.x, aR1[0]); aR1[1] = fmaf(x1, w2.y, aR1[1]);
        aR1[2] = fmaf(x1, w2.z, aR1[2]); aR1[3] = fmaf(x1, w2.w, aR1[3]);
    }

    const float4 bq = *(const float4*)&lb[e0];
    const float4 av = *(const float4*)&a[e0];
    float L0[4] = {aL0[0]+bq.x, aL0[1]+bq.y, aL0[2]+bq.z, aL0[3]+bq.w};
    float L1[4] = {aL1[0]+bq.x, aL1[1]+bq.y, aL1[2]+bq.z, aL1[3]+bq.w};

    *(float4*)&g_L[(b * KK + k0 + kq) * DD + e0]     = make_float4(L0[0], L0[1], L0[2], L0[3]);
    *(float4*)&g_L[(b * KK + k0 + kq + 1) * DD + e0] = make_float4(L1[0], L1[1], L1[2], L1[3]);
#pragma unroll
    for (int q = 0; q < 4; q++)
        *(float2*)&g_R[(b * DD + e0 + q) * KK + k0 + kq] = make_float2(aR0[q], aR1[q]);

    float pL0 = L0[0]*av.x + L0[1]*av.y + L0[2]*av.z + L0[3]*av.w;
    float pL1 = L1[0]*av.x + L1[1]*av.y + L1[2]*av.z + L1[3]*av.w;
    float pR0 = aR0[0]*av.x + aR0[1]*av.y + aR0[2]*av.z + aR0[3]*av.w;
    float pR1 = aR1[0]*av.x + aR1[1]*av.y + aR1[2]*av.z + aR1[3]*av.w;
    atomicAdd(&ssL[kq], pL0); atomicAdd(&ssL[kq + 1], pL1);
    atomicAdd(&ssR[kq], pR0); atomicAdd(&ssR[kq + 1], pR1);
    __syncthreads();

    for (int idx = tid; idx < 2048; idx += 256) {
        int k = idx >> 7, d = idx & 127;
        g_XT[(b * KK + k0 + k) * DD + d] = sx[d * 17 + k];
    }
    if (tid < 16) {
        g_sL[b * KK + k0 + tid] = ssL[tid];
        g_sR[b * KK + k0 + tid] = ssR[tid];
    }
}

// ---------------- Kernel 2: e -> softmax -> agg -> sigmoid+residual --------
__global__ __launch_bounds__(512) void k2(const float* __restrict__ a,
                                          const float* __restrict__ bias,
                                          float* __restrict__ out) {
    extern __shared__ float sm[];
    float* sLt = sm;               // [128][16] (reused as reduction buf)
    float* se  = sm + 2048;        // [16][512]
    float* buf = sm + 2048 + 8192; // [128][256] R chunk / [256][128] XT chunk
    __shared__ float sSL[16], sInv[16], sA[128];

    const int tid = threadIdx.x;
    const int b = blockIdx.x >> 5;
    const int i0 = (blockIdx.x & 31) << 4;

#pragma unroll
    for (int it = 0; it < 4; it++) {
        int idx = tid + it * 512;
        int i = idx >> 7, d = idx & 127;
        sLt[d * 16 + i] = g_L[(b * KK + i0 + i) * DD + d];
    }
    if (tid < 16) sSL[tid] = g_sL[b * KK + i0 + tid];
    if (tid < 128) sA[tid] = a[tid];

    const int jg = tid & 63, ip = (tid >> 6) * 2;

    // ---- e phase ----
    for (int jc = 0; jc < KK; jc += 256) {
        __syncthreads();
#pragma unroll
        for (int it = 0; it < 16; it++) {
            int idx = tid + it * 512;  // float4 units
            int d = idx >> 6, j4 = idx & 63;
            *(float4*)&buf[d * 256 + j4 * 4] =
                *(const float4*)&g_R[(b * DD + d) * KK + jc + j4 * 4];
        }
        __syncthreads();

        float a00=0,a01=0,a02=0,a03=0,a10=0,a11=0,a12=0,a13=0;
#pragma unroll 4
        for (int d = 0; d < 128; d++) {
            float avd = sA[d];
            float2 l = *(const float2*)&sLt[d * 16 + ip];
            float4 r = *(const float4*)&buf[d * 256 + jg * 4];
            float t;
            t = l.x + r.x; a00 = fmaf(fmaxf(t, 0.f), avd, a00);
            t = l.x + r.y; a01 = fmaf(fmaxf(t, 0.f), avd, a01);
            t = l.x + r.z; a02 = fmaf(fmaxf(t, 0.f), avd, a02);
            t = l.x + r.w; a03 = fmaf(fmaxf(t, 0.f), avd, a03);
            t = l.y + r.x; a10 = fmaf(fmaxf(t, 0.f), avd, a10);
            t = l.y + r.y; a11 = fmaf(fmaxf(t, 0.f), avd, a11);
            t = l.y + r.z; a12 = fmaf(fmaxf(t, 0.f), avd, a12);
            t = l.y + r.w; a13 = fmaf(fmaxf(t, 0.f), avd, a13);
        }

        const int j0 = jc + jg * 4;
        const float4 srv = *(const float4*)&g_sR[b * KK + j0];
        const float sl0 = sSL[ip], sl1 = sSL[ip + 1];
        const float4 bz0 = *(const float4*)&bias[(long)(i0 + ip) * KK + j0];
        const float4 bz1 = *(const float4*)&bias[(long)(i0 + ip + 1) * KK + j0];
        float4 e0v, e1v;
        e0v.x = ALPHA*(sl0+srv.x) + OMALPHA*a00 + bz0.x;
        e0v.y = ALPHA*(sl0+srv.y) + OMALPHA*a01 + bz0.y;
        e0v.z = ALPHA*(sl0+srv.z) + OMALPHA*a02 + bz0.z;
        e0v.w = ALPHA*(sl0+srv.w) + OMALPHA*a03 + bz0.w;
        e1v.x = ALPHA*(sl1+srv.x) + OMALPHA*a10 + bz1.x;
        e1v.y = ALPHA*(sl1+srv.y) + OMALPHA*a11 + bz1.y;
        e1v.z = ALPHA*(sl1+srv.z) + OMALPHA*a12 + bz1.z;
        e1v.w = ALPHA*(sl1+srv.w) + OMALPHA*a13 + bz1.w;
        *(float4*)&se[ip * KK + j0] = e0v;
        *(float4*)&se[(ip + 1) * KK + j0] = e1v;
    }
    __syncthreads();

    // ---- softmax: warp w -> row w, normalized in-place ----
    {
        const int w = tid >> 5, lane = tid & 31;
        float* row = se + w * KK;
        float v[16], m = -3.4e38f;
#pragma unroll
        for (int t = 0; t < 16; t++) { v[t] = row[t * 32 + lane]; m = fmaxf(m, v[t]); }
#pragma unroll
        for (int o = 16; o > 0; o >>= 1) m = fmaxf(m, __shfl_xor_sync(0xffffffffu, m, o));
        float s = 0.f;
#pragma unroll
        for (int t = 0; t < 16; t++) { v[t] = __expf(v[t] - m); s += v[t]; }
#pragma unroll
        for (int o = 16; o > 0; o >>= 1) s += __shfl_xor_sync(0xffffffffu, s, o);
        float inv = 1.f / s;
#pragma unroll
        for (int t = 0; t < 16; t++) row[t * 32 + lane] = v[t] * inv;
    }
    // zero reduction buffer (reuse sLt)
    for (int idx = tid; idx < 2048; idx += 512) sLt[idx] = 0.f;
    __syncthreads();

    // ---- agg: attn @ XT, 4i x 4d per thread, 4 j-slices ----
    const int dg = tid & 31, q = tid >> 5;
    const int igr = (q & 3) * 4, js = (q >> 2) * 64;
    float ag[4][4] = {{0,0,0,0},{0,0,0,0},{0,0,0,0},{0,0,0,0}};

    for (int jc = 0; jc < KK; jc += 256) {
#pragma unroll
        for (int it = 0; it < 16; it++) {
            int idx = tid + it * 512;  // float4 units
            int j = idx >> 5, d4 = idx & 31;
            *(float4*)&buf[j * 128 + d4 * 4] =
                *(const float4*)&g_XT[(b * KK + jc + j) * DD + d4 * 4];
        }
        __syncthreads();
#pragma unroll 2
        for (int t = 0; t < 64; t++) {
            int j = js + t;
            float4 xv = *(const float4*)&buf[j * 128 + dg * 4];
#pragma unroll
            for (int r = 0; r < 4; r++) {
                float at = se[(igr + r) * KK + jc + j];
                ag[r][0] = fmaf(at, xv.x, ag[r][0]);
                ag[r][1] = fmaf(at, xv.y, ag[r][1]);
                ag[r][2] = fmaf(at, xv.z, ag[r][2]);
                ag[r][3] = fmaf(at, xv.w, ag[r][3]);
            }
        }
        __syncthreads();
    }
#pragma unroll
    for (int r = 0; r < 4; r++)
#pragma unroll
        for (int c = 0; c < 4; c++)
            atomicAdd(&sLt[(igr + r) * 128 + dg * 4 + c], ag[r][c]);
    __syncthreads();

    // ---- epilogue: sigmoid + residual, write transposed ----
    for (int idx = tid; idx < 2048; idx += 512) {
        int i = idx & 15, d = idx >> 4;
        float v = sLt[i * 128 + d];
        float sg = 1.f / (1.f + __expf(-v));
        float xt = g_XT[(b * KK + i0 + i) * DD + d];
        out[(b * DD + d) * KK + i0 + i] = sg + xt;
    }
}

extern "C" void kernel_launch(void* const* d_in, const int* in_sizes, int n_in,
                              void* d_out, int out_size) {
    const float* x    = (const float*)d_in[0];
    const float* lw   = (const float*)d_in[1];
    const float* lb   = (const float*)d_in[2];
    const float* a    = (const float*)d_in[3];
    const float* bias = (const float*)d_in[4];
    float* out = (float*)d_out;

    static bool attr_set = false;
    if (!attr_set) {
        cudaFuncSetAttribute(k2, cudaFuncAttributeMaxDynamicSharedMemorySize,
                             (2048 + 8192 + 32768) * 4);
        attr_set = true;
    }
    k1<<<128, 256>>>(x, lw, lb, a);
    k2<<<128, 512, (2048 + 8192 + 32768) * 4>>>(a, bias, out);
}

// round 4
// speedup vs baseline: 1.1373x; 1.1373x over previous
#include <cuda_runtime.h>

#define BB 4
#define DD 128
#define KK 512
#define ALPHA 0.2f
#define OMALPHA 0.8f

__device__ float g_L[BB * KK * DD];   // [b][k][e]
__device__ float g_R[BB * DD * KK];   // [b][e][k]  (d-major)
__device__ float g_XT[BB * KK * DD];  // [b][k][d]
__device__ float g_sL[BB * KK];
__device__ float g_sR[BB * KK];

// ---------------- Kernel 1: L,R GEMMs + sL,sR + XT transpose ----------------
// grid 256 = B * (K/8), 256 threads
__global__ __launch_bounds__(256) void k1(const float* __restrict__ x,
                                          const float* __restrict__ lw,
                                          const float* __restrict__ lb,
                                          const float* __restrict__ a) {
    __shared__ float sx[128 * 9];  // [d][k], k<8, pad 9
    const int tid = threadIdx.x;
    const int b = blockIdx.x >> 6;
    const int k0 = (blockIdx.x & 63) << 3;

    for (int idx = tid; idx < 1024; idx += 256) {
        int d = idx >> 3, k = idx & 7;
        sx[d * 9 + k] = x[(b * DD + d) * KK + k0 + k];
    }
    __syncthreads();

    const int eg = tid & 31, e0 = eg * 4;
    const int kq = tid >> 5;  // warp id == local k
    float aL[4] = {0, 0, 0, 0}, aR[4] = {0, 0, 0, 0};

#pragma unroll 4
    for (int d = 0; d < 128; d++) {
        float xv = sx[d * 9 + kq];
        float4 w1 = *(const float4*)&lw[d * 128 + e0];
        float4 w2 = *(const float4*)&lw[(128 + d) * 128 + e0];
        aL[0] = fmaf(xv, w1.x, aL[0]); aL[1] = fmaf(xv, w1.y, aL[1]);
        aL[2] = fmaf(xv, w1.z, aL[2]); aL[3] = fmaf(xv, w1.w, aL[3]);
        aR[0] = fmaf(xv, w2.x, aR[0]); aR[1] = fmaf(xv, w2.y, aR[1]);
        aR[2] = fmaf(xv, w2.z, aR[2]); aR[3] = fmaf(xv, w2.w, aR[3]);
    }

    const float4 bq = *(const float4*)&lb[e0];
    const float4 av = *(const float4*)&a[e0];
    float4 Lv = make_float4(aL[0] + bq.x, aL[1] + bq.y, aL[2] + bq.z, aL[3] + bq.w);

    *(float4*)&g_L[(b * KK + k0 + kq) * DD + e0] = Lv;
#pragma unroll
    for (int q = 0; q < 4; q++)
        g_R[(b * DD + e0 + q) * KK + k0 + kq] = aR[q];

    float pL = Lv.x * av.x + Lv.y * av.y + Lv.z * av.z + Lv.w * av.w;
    float pR = aR[0] * av.x + aR[1] * av.y + aR[2] * av.z + aR[3] * av.w;
#pragma unroll
    for (int o = 16; o > 0; o >>= 1) {
        pL += __shfl_xor_sync(0xffffffffu, pL, o);
        pR += __shfl_xor_sync(0xffffffffu, pR, o);
    }
    if (eg == 0) {
        g_sL[b * KK + k0 + kq] = pL;
        g_sR[b * KK + k0 + kq] = pR;
    }

    for (int idx = tid; idx < 1024; idx += 256) {
        int k = idx >> 7, d = idx & 127;
        g_XT[(b * KK + k0 + k) * DD + d] = sx[d * 9 + k];
    }
}

// ---------------- Kernel 2: e -> softmax -> agg -> sigmoid+residual --------
// grid 256 = B * (K/8), 256 threads, ~60KB smem -> 2 CTAs/SM
// smem: sLt[128][8] (1024) | part[2][8][512] (8192) | seJI[512][12] (6144)
#define SM_PART 1024
#define SM_SE   9216
#define SM_TOT  15360

__global__ __launch_bounds__(256, 2) void k2(const float* __restrict__ a,
                                             const float* __restrict__ bias,
                                             float* __restrict__ out) {
    extern __shared__ float sm[];
    float* sLt  = sm;            // [d][i] d*8+i
    float* part = sm + SM_PART;  // [sp][i][j] sp*4096 + i*512 + j
    float* seJI = sm + SM_SE;    // [j][i] j*12+i (pad 12)
    __shared__ float sSL[8], sA[128];

    const int tid = threadIdx.x;
    const int b = blockIdx.x >> 6;
    const int i0 = (blockIdx.x & 63) << 3;

#pragma unroll
    for (int it = 0; it < 4; it++) {
        int idx = tid + it * 256;
        int d = idx >> 3, i = idx & 7;
        sLt[idx] = g_L[(b * KK + i0 + i) * DD + d];
    }
    if (tid < 8) sSL[tid] = g_sL[b * KK + i0 + tid];
    if (tid < 128) sA[tid] = a[tid];
    __syncthreads();

    // ---- e phase: split-d, each thread 8i x 4j over 64 d ----
    const int jq = tid & 127;      // j-quad -> j0 = jq*4
    const int sp = tid >> 7;       // d-split 0/1
    const float* Rb = g_R + (b * DD + sp * 64) * KK;
    float acc[8][4];
#pragma unroll
    for (int i = 0; i < 8; i++) { acc[i][0] = 0; acc[i][1] = 0; acc[i][2] = 0; acc[i][3] = 0; }

#pragma unroll 2
    for (int dd = 0; dd < 64; dd++) {
        const int d = sp * 64 + dd;
        float4 r = *(const float4*)&Rb[dd * KK + jq * 4];
        float av = sA[d];
        float lt[8];
        *(float4*)&lt[0] = *(const float4*)&sLt[d * 8];
        *(float4*)&lt[4] = *(const float4*)&sLt[d * 8 + 4];
#pragma unroll
        for (int i = 0; i < 8; i++) {
            float t;
            t = lt[i] + r.x; acc[i][0] = fmaf(fmaxf(t, 0.f), av, acc[i][0]);
            t = lt[i] + r.y; acc[i][1] = fmaf(fmaxf(t, 0.f), av, acc[i][1]);
            t = lt[i] + r.z; acc[i][2] = fmaf(fmaxf(t, 0.f), av, acc[i][2]);
            t = lt[i] + r.w; acc[i][3] = fmaf(fmaxf(t, 0.f), av, acc[i][3]);
        }
    }
    {
        float* pp = part + sp * 4096;
#pragma unroll
        for (int i = 0; i < 8; i++)
            *(float4*)&pp[i * KK + jq * 4] = make_float4(acc[i][0], acc[i][1], acc[i][2], acc[i][3]);
    }
    __syncthreads();

    // ---- combine partials + linear term + bias -> seJI[j][i] ----
    {
        const int jq2 = tid & 127;
        const int ih0 = (tid >> 7) * 4;
        float4 sr = *(const float4*)&g_sR[b * KK + jq2 * 4];
#pragma unroll
        for (int r = 0; r < 4; r++) {
            int i = ih0 + r;
            float4 p0 = *(const float4*)&part[i * KK + jq2 * 4];
            float4 p1 = *(const float4*)&part[4096 + i * KK + jq2 * 4];
            float4 bz = *(const float4*)&bias[(long)(i0 + i) * KK + jq2 * 4];
            float sl = sSL[i];
            seJI[(jq2 * 4 + 0) * 12 + i] = ALPHA * (sl + sr.x) + OMALPHA * (p0.x + p1.x) + bz.x;
            seJI[(jq2 * 4 + 1) * 12 + i] = ALPHA * (sl + sr.y) + OMALPHA * (p0.y + p1.y) + bz.y;
            seJI[(jq2 * 4 + 2) * 12 + i] = ALPHA * (sl + sr.z) + OMALPHA * (p0.z + p1.z) + bz.z;
            seJI[(jq2 * 4 + 3) * 12 + i] = ALPHA * (sl + sr.w) + OMALPHA * (p0.w + p1.w) + bz.w;
        }
    }
    __syncthreads();

    // ---- softmax: warp w -> row i=w (8 warps) ----
    {
        const int w = tid >> 5, lane = tid & 31;
        float v[16], m = -3.4e38f;
#pragma unroll
        for (int t = 0; t < 16; t++) { v[t] = seJI[(t * 32 + lane) * 12 + w]; m = fmaxf(m, v[t]); }
#pragma unroll
        for (int o = 16; o > 0; o >>= 1) m = fmaxf(m, __shfl_xor_sync(0xffffffffu, m, o));
        float s = 0.f;
#pragma unroll
        for (int t = 0; t < 16; t++) { v[t] = __expf(v[t] - m); s += v[t]; }
#pragma unroll
        for (int o = 16; o > 0; o >>= 1) s += __shfl_xor_sync(0xffffffffu, s, o);
        float inv = 1.f / s;
#pragma unroll
        for (int t = 0; t < 16; t++) seJI[(t * 32 + lane) * 12 + w] = v[t] * inv;
    }
    __syncthreads();

    // ---- agg: attn @ XT, thread = (j-slice, d-quad), owns all 8 i ----
    const int d4 = tid & 31;
    const int js = tid >> 5;
    float4 ag[8];
#pragma unroll
    for (int i = 0; i < 8; i++) ag[i] = make_float4(0.f, 0.f, 0.f, 0.f);

#pragma unroll 2
    for (int t = 0; t < 64; t++) {
        int j = js * 64 + t;
        float4 xv = *(const float4*)&g_XT[(b * KK + j) * DD + d4 * 4];
        float at[8];
        *(float4*)&at[0] = *(const float4*)&seJI[j * 12];
        *(float4*)&at[4] = *(const float4*)&seJI[j * 12 + 4];
#pragma unroll
        for (int i = 0; i < 8; i++) {
            ag[i].x = fmaf(at[i], xv.x, ag[i].x);
            ag[i].y = fmaf(at[i], xv.y, ag[i].y);
            ag[i].z = fmaf(at[i], xv.z, ag[i].z);
            ag[i].w = fmaf(at[i], xv.w, ag[i].w);
        }
    }
    __syncthreads();
    float* red = part;  // reuse: [js][i][d] js*1024 + i*128 + d
#pragma unroll
    for (int i = 0; i < 8; i++)
        *(float4*)&red[js * 1024 + i * 128 + d4 * 4] = ag[i];
    __syncthreads();

    // ---- reduce over j-slices + sigmoid + residual ----
    {
        const int i2 = tid >> 5;
        const int dq = (tid & 31) * 4;
        float4 s = make_float4(0.f, 0.f, 0.f, 0.f);
#pragma unroll
        for (int r = 0; r < 8; r++) {
            float4 p = *(const float4*)&red[r * 1024 + i2 * 128 + dq];
            s.x += p.x; s.y += p.y; s.z += p.z; s.w += p.w;
        }
        float4 xt = *(const float4*)&g_XT[(b * KK + i0 + i2) * DD + dq];
        out[(b * DD + dq + 0) * KK + i0 + i2] = 1.f / (1.f + __expf(-s.x)) + xt.x;
        out[(b * DD + dq + 1) * KK + i0 + i2] = 1.f / (1.f + __expf(-s.y)) + xt.y;
        out[(b * DD + dq + 2) * KK + i0 + i2] = 1.f / (1.f + __expf(-s.z)) + xt.z;
        out[(b * DD + dq + 3) * KK + i0 + i2] = 1.f / (1.f + __expf(-s.w)) + xt.w;
    }
}

extern "C" void kernel_launch(void* const* d_in, const int* in_sizes, int n_in,
                              void* d_out, int out_size) {
    const float* x    = (const float*)d_in[0];
    const float* lw   = (const float*)d_in[1];
    const float* lb   = (const float*)d_in[2];
    const float* a    = (const float*)d_in[3];
    const float* bias = (const float*)d_in[4];
    float* out = (float*)d_out;

    static bool attr_set = false;
    if (!attr_set) {
        cudaFuncSetAttribute(k2, cudaFuncAttributeMaxDynamicSharedMemorySize, SM_TOT * 4);
        attr_set = true;
    }
    k1<<<256, 256>>>(x, lw, lb, a);
    k2<<<256, 256, SM_TOT * 4>>>(a, bias, out);
}

// round 5
// speedup vs baseline: 1.2774x; 1.1232x over previous
#include <cuda_runtime.h>

#define BB 4
#define DD 128
#define KK 512
// e = C1*(sL+sR) + C2*sum|t|a + bias, with alpha=0.2
#define C1 0.6f
#define C2 0.4f

typedef unsigned long long ull;
#define ABSM 0x7FFFFFFF7FFFFFFFULL

__device__ __forceinline__ ull uadd2(ull a, ull b) {
    ull r; asm("add.rn.f32x2 %0,%1,%2;" : "=l"(r) : "l"(a), "l"(b)); return r;
}
__device__ __forceinline__ ull ufma2(ull a, ull b, ull c) {
    ull r; asm("fma.rn.f32x2 %0,%1,%2,%3;" : "=l"(r) : "l"(a), "l"(b), "l"(c)); return r;
}
__device__ __forceinline__ ull bc2(float x) {
    ull r; asm("mov.b64 %0,{%1,%1};" : "=l"(r) : "f"(x)); return r;
}
__device__ __forceinline__ ull pk2(float x, float y) {
    ull r; asm("mov.b64 %0,{%1,%2};" : "=l"(r) : "f"(x), "f"(y)); return r;
}
__device__ __forceinline__ float2 up2(ull v) {
    float2 f; asm("mov.b64 {%0,%1},%2;" : "=f"(f.x), "=f"(f.y) : "l"(v)); return f;
}

__device__ float g_L[BB * KK * DD];   // [b][k][e]
__device__ float g_R[BB * DD * KK];   // [b][e][k]  (d-major)
__device__ float g_XT[BB * KK * DD];  // [b][k][d]
__device__ float g_sL[BB * KK];
__device__ float g_sR[BB * KK];

// ---------------- Kernel 1: L,R GEMMs + sL,sR + XT transpose ----------------
__global__ __launch_bounds__(256) void k1(const float* __restrict__ x,
                                          const float* __restrict__ lw,
                                          const float* __restrict__ lb,
                                          const float* __restrict__ a) {
    __shared__ float sx[128 * 9];
    const int tid = threadIdx.x;
    const int b = blockIdx.x >> 6;
    const int k0 = (blockIdx.x & 63) << 3;

    for (int idx = tid; idx < 1024; idx += 256) {
        int d = idx >> 3, k = idx & 7;
        sx[d * 9 + k] = x[(b * DD + d) * KK + k0 + k];
    }
    __syncthreads();

    const int eg = tid & 31, e0 = eg * 4;
    const int kq = tid >> 5;
    float aL[4] = {0, 0, 0, 0}, aR[4] = {0, 0, 0, 0};

#pragma unroll 4
    for (int d = 0; d < 128; d++) {
        float xv = sx[d * 9 + kq];
        float4 w1 = *(const float4*)&lw[d * 128 + e0];
        float4 w2 = *(const float4*)&lw[(128 + d) * 128 + e0];
        aL[0] = fmaf(xv, w1.x, aL[0]); aL[1] = fmaf(xv, w1.y, aL[1]);
        aL[2] = fmaf(xv, w1.z, aL[2]); aL[3] = fmaf(xv, w1.w, aL[3]);
        aR[0] = fmaf(xv, w2.x, aR[0]); aR[1] = fmaf(xv, w2.y, aR[1]);
        aR[2] = fmaf(xv, w2.z, aR[2]); aR[3] = fmaf(xv, w2.w, aR[3]);
    }

    const float4 bq = *(const float4*)&lb[e0];
    const float4 av = *(const float4*)&a[e0];
    float4 Lv = make_float4(aL[0] + bq.x, aL[1] + bq.y, aL[2] + bq.z, aL[3] + bq.w);

    *(float4*)&g_L[(b * KK + k0 + kq) * DD + e0] = Lv;
#pragma unroll
    for (int q = 0; q < 4; q++)
        g_R[(b * DD + e0 + q) * KK + k0 + kq] = aR[q];

    float pL = Lv.x * av.x + Lv.y * av.y + Lv.z * av.z + Lv.w * av.w;
    float pR = aR[0] * av.x + aR[1] * av.y + aR[2] * av.z + aR[3] * av.w;
#pragma unroll
    for (int o = 16; o > 0; o >>= 1) {
        pL += __shfl_xor_sync(0xffffffffu, pL, o);
        pR += __shfl_xor_sync(0xffffffffu, pR, o);
    }
    if (eg == 0) {
        g_sL[b * KK + k0 + kq] = pL;
        g_sR[b * KK + k0 + kq] = pR;
    }

    for (int idx = tid; idx < 1024; idx += 256) {
        int k = idx >> 7, d = idx & 127;
        g_XT[(b * KK + k0 + k) * DD + d] = sx[d * 9 + k];
    }
}

// ---------------- Kernel 2 ----------------
// smem floats: sLd[128][8] dup-pairs @0 (2048) | sAd[128] dup @2048 (256)
//              part[2][8][512] @2304 (8192) | se[8][512] @10496 (4096)
#define OF_SAD  2048
#define OF_PART 2304
#define OF_SE   10496
#define SM_FLTS 14592

__global__ __launch_bounds__(256, 2) void k2(const float* __restrict__ a,
                                             const float* __restrict__ bias,
                                             float* __restrict__ out) {
    extern __shared__ float sm[];
    ull*   sLd  = (ull*)sm;            // [d][i] dup pairs
    ull*   sAd  = (ull*)(sm + OF_SAD); // [d] dup pairs
    float* part = sm + OF_PART;        // [sp][i][j]
    float* se   = sm + OF_SE;          // [i][j]
    __shared__ float sSL[8];

    const int tid = threadIdx.x;
    const int b = blockIdx.x >> 6;
    const int i0 = (blockIdx.x & 63) << 3;

    for (int idx = tid; idx < 1024; idx += 256) {
        int d = idx >> 3, i = idx & 7;
        sLd[idx] = bc2(g_L[(b * KK + i0 + i) * DD + d]);
    }
    if (tid < 128) sAd[tid] = bc2(a[tid]);
    if (tid < 8) sSL[tid] = g_sL[b * KK + i0 + tid];
    __syncthreads();

    // ---- e phase: split-d (sp), thread = 4 j (2 packed j-pairs) x 8 i ----
    {
        const int jq = tid & 127;
        const int sp = tid >> 7;
        const float* Rb = g_R + (b * DD + sp * 64) * KK + jq * 4;
        const ull* sLdsp = sLd + sp * 64 * 8;
        const ull* sAdsp = sAd + sp * 64;
        ull acc[8][2];
#pragma unroll
        for (int i = 0; i < 8; i++) { acc[i][0] = 0ull; acc[i][1] = 0ull; }

#pragma unroll 4
        for (int dd = 0; dd < 64; dd++) {
            float4 rq = *(const float4*)(Rb + dd * KK);
            ull r01 = pk2(rq.x, rq.y), r23 = pk2(rq.z, rq.w);
            ull av2 = sAdsp[dd];
#pragma unroll
            for (int i = 0; i < 8; i++) {
                ull l2 = sLdsp[dd * 8 + i];
                ull u0 = uadd2(l2, r01) & ABSM;
                ull u1 = uadd2(l2, r23) & ABSM;
                acc[i][0] = ufma2(u0, av2, acc[i][0]);
                acc[i][1] = ufma2(u1, av2, acc[i][1]);
            }
        }
        float* pp = part + sp * 4096 + jq * 4;
#pragma unroll
        for (int i = 0; i < 8; i++) {
            float2 q0 = up2(acc[i][0]), q1 = up2(acc[i][1]);
            *(float4*)&pp[i * KK] = make_float4(q0.x, q0.y, q1.x, q1.y);
        }
    }
    __syncthreads();

    // ---- combine: e = C1*(sL+sR) + C2*(p0+p1) + bias -> se[i][j] ----
    {
        const int jq2 = tid & 127;
        const int ih0 = (tid >> 7) * 4;
        float4 sr = *(const float4*)&g_sR[b * KK + jq2 * 4];
#pragma unroll
        for (int r = 0; r < 4; r++) {
            int i = ih0 + r;
            float4 p0 = *(const float4*)&part[i * KK + jq2 * 4];
            float4 p1 = *(const float4*)&part[4096 + i * KK + jq2 * 4];
            float4 bz = *(const float4*)&bias[(long)(i0 + i) * KK + jq2 * 4];
            float sl = sSL[i];
            float4 ev;
            ev.x = C1 * (sl + sr.x) + C2 * (p0.x + p1.x) + bz.x;
            ev.y = C1 * (sl + sr.y) + C2 * (p0.y + p1.y) + bz.y;
            ev.z = C1 * (sl + sr.z) + C2 * (p0.z + p1.z) + bz.z;
            ev.w = C1 * (sl + sr.w) + C2 * (p0.w + p1.w) + bz.w;
            *(float4*)&se[i * KK + jq2 * 4] = ev;
        }
    }
    __syncthreads();

    // ---- softmax: warp w -> row i=w ----
    {
        const int w = tid >> 5, lane = tid & 31;
        float* row = se + w * KK;
        float v[16], m = -3.4e38f;
#pragma unroll
        for (int t = 0; t < 16; t++) { v[t] = row[t * 32 + lane]; m = fmaxf(m, v[t]); }
#pragma unroll
        for (int o = 16; o > 0; o >>= 1) m = fmaxf(m, __shfl_xor_sync(0xffffffffu, m, o));
        float s = 0.f;
#pragma unroll
        for (int t = 0; t < 16; t++) { v[t] = __expf(v[t] - m); s += v[t]; }
#pragma unroll
        for (int o = 16; o > 0; o >>= 1) s += __shfl_xor_sync(0xffffffffu, s, o);
        float inv = 1.f / s;
#pragma unroll
        for (int t = 0; t < 16; t++) row[t * 32 + lane] = v[t] * inv;
    }
    __syncthreads();

    // ---- agg: attn @ XT, thread = (j-slice, d-quad), d packed in pairs ----
    const int d4 = tid & 31;
    const int js = tid >> 5;
    {
        const float* Xb = g_XT + (b * KK + js * 64) * DD + d4 * 4;
        ull ag[8][2];
#pragma unroll
        for (int i = 0; i < 8; i++) { ag[i][0] = 0ull; ag[i][1] = 0ull; }

#pragma unroll 4
        for (int t = 0; t < 64; t++) {
            float4 xq = *(const float4*)(Xb + t * DD);
            ull x01 = pk2(xq.x, xq.y), x23 = pk2(xq.z, xq.w);
            const int j = js * 64 + t;
#pragma unroll
            for (int i = 0; i < 8; i++) {
                ull a2 = bc2(se[i * KK + j]);
                ag[i][0] = ufma2(a2, x01, ag[i][0]);
                ag[i][1] = ufma2(a2, x23, ag[i][1]);
            }
        }
        // write partial results (reuse part as red[js][i][d])
        float* red = part;
#pragma unroll
        for (int i = 0; i < 8; i++) {
            float2 q0 = up2(ag[i][0]), q1 = up2(ag[i][1]);
            *(float4*)&red[js * 1024 + i * 128 + d4 * 4] =
                make_float4(q0.x, q0.y, q1.x, q1.y);
        }
    }
    __syncthreads();

    // ---- reduce over j-slices + sigmoid + residual ----
    {
        const float* red = part;
        const int i2 = tid >> 5;
        const int dq = (tid & 31) * 4;
        float4 s = make_float4(0.f, 0.f, 0.f, 0.f);
#pragma unroll
        for (int r = 0; r < 8; r++) {
            float4 p = *(const float4*)&red[r * 1024 + i2 * 128 + dq];
            s.x += p.x; s.y += p.y; s.z += p.z; s.w += p.w;
        }
        float4 xt = *(const float4*)&g_XT[(b * KK + i0 + i2) * DD + dq];
        out[(b * DD + dq + 0) * KK + i0 + i2] = 1.f / (1.f + __expf(-s.x)) + xt.x;
        out[(b * DD + dq + 1) * KK + i0 + i2] = 1.f / (1.f + __expf(-s.y)) + xt.y;
        out[(b * DD + dq + 2) * KK + i0 + i2] = 1.f / (1.f + __expf(-s.z)) + xt.z;
        out[(b * DD + dq + 3) * KK + i0 + i2] = 1.f / (1.f + __expf(-s.w)) + xt.w;
    }
}

extern "C" void kernel_launch(void* const* d_in, const int* in_sizes, int n_in,
                              void* d_out, int out_size) {
    const float* x    = (const float*)d_in[0];
    const float* lw   = (const float*)d_in[1];
    const float* lb   = (const float*)d_in[2];
    const float* a    = (const float*)d_in[3];
    const float* bias = (const float*)d_in[4];
    float* out = (float*)d_out;

    static bool attr_set = false;
    if (!attr_set) {
        cudaFuncSetAttribute(k2, cudaFuncAttributeMaxDynamicSharedMemorySize,
                             SM_FLTS * 4);
        attr_set = true;
    }
    k1<<<256, 256>>>(x, lw, lb, a);
    k2<<<256, 256, SM_FLTS * 4>>>(a, bias, out);
}

// round 6
// speedup vs baseline: 1.3310x; 1.0419x over previous
#include <cuda_runtime.h>

#define BB 4
#define DD 128
#define KK 512
// e = C1*(sL+sR) + C2*sum|t|a + bias, with alpha=0.2
#define C1 0.6f
#define C2 0.4f

typedef unsigned long long ull;
#define ABSM 0x7FFFFFFF7FFFFFFFULL

__device__ __forceinline__ ull uadd2(ull a, ull b) {
    ull r; asm("add.rn.f32x2 %0,%1,%2;" : "=l"(r) : "l"(a), "l"(b)); return r;
}
__device__ __forceinline__ ull ufma2(ull a, ull b, ull c) {
    ull r; asm("fma.rn.f32x2 %0,%1,%2,%3;" : "=l"(r) : "l"(a), "l"(b), "l"(c)); return r;
}
__device__ __forceinline__ ull bc2(float x) {
    ull r; asm("mov.b64 %0,{%1,%1};" : "=l"(r) : "f"(x)); return r;
}
__device__ __forceinline__ ull pk2(float x, float y) {
    ull r; asm("mov.b64 %0,{%1,%2};" : "=l"(r) : "f"(x), "f"(y)); return r;
}
__device__ __forceinline__ float2 up2(ull v) {
    float2 f; asm("mov.b64 {%0,%1},%2;" : "=f"(f.x), "=f"(f.y) : "l"(v)); return f;
}

__device__ float g_L[BB * KK * DD];   // [b][k][e]
__device__ float g_R[BB * DD * KK];   // [b][e][k]  (d-major)
__device__ float g_XT[BB * KK * DD];  // [b][k][d]
__device__ float g_sL[BB * KK];
__device__ float g_sR[BB * KK];

// ---------------- Kernel 1: L,R GEMMs + sL,sR + XT transpose ----------------
__global__ __launch_bounds__(256) void k1(const float* __restrict__ x,
                                          const float* __restrict__ lw,
                                          const float* __restrict__ lb,
                                          const float* __restrict__ a) {
    __shared__ float sx[128 * 9];
    const int tid = threadIdx.x;
    const int b = blockIdx.x >> 6;
    const int k0 = (blockIdx.x & 63) << 3;

    for (int idx = tid; idx < 1024; idx += 256) {
        int d = idx >> 3, k = idx & 7;
        sx[d * 9 + k] = x[(b * DD + d) * KK + k0 + k];
    }
    __syncthreads();

    const int eg = tid & 31, e0 = eg * 4;
    const int kq = tid >> 5;
    float aL[4] = {0, 0, 0, 0}, aR[4] = {0, 0, 0, 0};

#pragma unroll 8
    for (int d = 0; d < 128; d++) {
        float xv = sx[d * 9 + kq];
        float4 w1 = *(const float4*)&lw[d * 128 + e0];
        float4 w2 = *(const float4*)&lw[(128 + d) * 128 + e0];
        aL[0] = fmaf(xv, w1.x, aL[0]); aL[1] = fmaf(xv, w1.y, aL[1]);
        aL[2] = fmaf(xv, w1.z, aL[2]); aL[3] = fmaf(xv, w1.w, aL[3]);
        aR[0] = fmaf(xv, w2.x, aR[0]); aR[1] = fmaf(xv, w2.y, aR[1]);
        aR[2] = fmaf(xv, w2.z, aR[2]); aR[3] = fmaf(xv, w2.w, aR[3]);
    }

    const float4 bq = *(const float4*)&lb[e0];
    const float4 av = *(const float4*)&a[e0];
    float4 Lv = make_float4(aL[0] + bq.x, aL[1] + bq.y, aL[2] + bq.z, aL[3] + bq.w);

    *(float4*)&g_L[(b * KK + k0 + kq) * DD + e0] = Lv;
#pragma unroll
    for (int q = 0; q < 4; q++)
        g_R[(b * DD + e0 + q) * KK + k0 + kq] = aR[q];

    float pL = Lv.x * av.x + Lv.y * av.y + Lv.z * av.z + Lv.w * av.w;
    float pR = aR[0] * av.x + aR[1] * av.y + aR[2] * av.z + aR[3] * av.w;
#pragma unroll
    for (int o = 16; o > 0; o >>= 1) {
        pL += __shfl_xor_sync(0xffffffffu, pL, o);
        pR += __shfl_xor_sync(0xffffffffu, pR, o);
    }
    if (eg == 0) {
        g_sL[b * KK + k0 + kq] = pL;
        g_sR[b * KK + k0 + kq] = pR;
    }

    for (int idx = tid; idx < 1024; idx += 256) {
        int k = idx >> 7, d = idx & 127;
        g_XT[(b * KK + k0 + k) * DD + d] = sx[d * 9 + k];
    }
}

// ---------------- Kernel 2 ----------------
// smem floats: sLd[128][8] dup-pairs @0 (2048) | sAd[128] dup @2048 (256)
//              part[2][8][512] @2304 (8192) | se[8][512] @10496 (4096)
#define OF_SAD  2048
#define OF_PART 2304
#define OF_SE   10496
#define SM_FLTS 14592

__global__ __launch_bounds__(256, 2) void k2(const float* __restrict__ a,
                                             const float* __restrict__ bias,
                                             float* __restrict__ out) {
    extern __shared__ float sm[];
    ull*   sLd  = (ull*)sm;            // [d][i] dup pairs
    ull*   sAd  = (ull*)(sm + OF_SAD); // [d] dup pairs
    float* part = sm + OF_PART;        // [sp][i][j]
    float* se   = sm + OF_SE;          // [i][j]
    __shared__ float sSL[8];

    const int tid = threadIdx.x;
    const int b = blockIdx.x >> 6;
    const int i0 = (blockIdx.x & 63) << 3;

    for (int idx = tid; idx < 1024; idx += 256) {
        int d = idx >> 3, i = idx & 7;
        sLd[idx] = bc2(g_L[(b * KK + i0 + i) * DD + d]);
    }
    if (tid < 128) sAd[tid] = bc2(a[tid]);
    if (tid < 8) sSL[tid] = g_sL[b * KK + i0 + tid];
    __syncthreads();

    // ---- e phase: split-d (sp), thread = 4 j (2 packed j-pairs) x 8 i ----
    {
        const int jq = tid & 127;
        const int sp = tid >> 7;
        const float* Rb = g_R + (b * DD + sp * 64) * KK + jq * 4;
        const ull* sLdsp = sLd + sp * 64 * 8;
        const ull* sAdsp = sAd + sp * 64;
        ull acc[8][2];
#pragma unroll
        for (int i = 0; i < 8; i++) { acc[i][0] = 0ull; acc[i][1] = 0ull; }

#pragma unroll 8
        for (int dd = 0; dd < 64; dd++) {
            float4 rq = *(const float4*)(Rb + dd * KK);
            ull r01 = pk2(rq.x, rq.y), r23 = pk2(rq.z, rq.w);
            ull av2 = sAdsp[dd];
#pragma unroll
            for (int i = 0; i < 8; i++) {
                ull l2 = sLdsp[dd * 8 + i];
                ull u0 = uadd2(l2, r01) & ABSM;
                ull u1 = uadd2(l2, r23) & ABSM;
                acc[i][0] = ufma2(u0, av2, acc[i][0]);
                acc[i][1] = ufma2(u1, av2, acc[i][1]);
            }
        }
        float* pp = part + sp * 4096 + jq * 4;
#pragma unroll
        for (int i = 0; i < 8; i++) {
            float2 q0 = up2(acc[i][0]), q1 = up2(acc[i][1]);
            *(float4*)&pp[i * KK] = make_float4(q0.x, q0.y, q1.x, q1.y);
        }
    }
    __syncthreads();

    // ---- combine: e = C1*(sL+sR) + C2*(p0+p1) + bias -> se[i][j] ----
    {
        const int jq2 = tid & 127;
        const int ih0 = (tid >> 7) * 4;
        float4 sr = *(const float4*)&g_sR[b * KK + jq2 * 4];
#pragma unroll
        for (int r = 0; r < 4; r++) {
            int i = ih0 + r;
            float4 p0 = *(const float4*)&part[i * KK + jq2 * 4];
            float4 p1 = *(const float4*)&part[4096 + i * KK + jq2 * 4];
            float4 bz = *(const float4*)&bias[(long)(i0 + i) * KK + jq2 * 4];
            float sl = sSL[i];
            float4 ev;
            ev.x = C1 * (sl + sr.x) + C2 * (p0.x + p1.x) + bz.x;
            ev.y = C1 * (sl + sr.y) + C2 * (p0.y + p1.y) + bz.y;
            ev.z = C1 * (sl + sr.z) + C2 * (p0.z + p1.z) + bz.z;
            ev.w = C1 * (sl + sr.w) + C2 * (p0.w + p1.w) + bz.w;
            *(float4*)&se[i * KK + jq2 * 4] = ev;
        }
    }
    __syncthreads();

    // ---- softmax: warp w -> row i=w ----
    {
        const int w = tid >> 5, lane = tid & 31;
        float* row = se + w * KK;
        float v[16], m = -3.4e38f;
#pragma unroll
        for (int t = 0; t < 16; t++) { v[t] = row[t * 32 + lane]; m = fmaxf(m, v[t]); }
#pragma unroll
        for (int o = 16; o > 0; o >>= 1) m = fmaxf(m, __shfl_xor_sync(0xffffffffu, m, o));
        float s = 0.f;
#pragma unroll
        for (int t = 0; t < 16; t++) { v[t] = __expf(v[t] - m); s += v[t]; }
#pragma unroll
        for (int o = 16; o > 0; o >>= 1) s += __shfl_xor_sync(0xffffffffu, s, o);
        float inv = 1.f / s;
#pragma unroll
        for (int t = 0; t < 16; t++) row[t * 32 + lane] = v[t] * inv;
    }
    __syncthreads();

    // ---- agg: attn @ XT, thread = (j-slice, d-quad), d packed in pairs ----
    const int d4 = tid & 31;
    const int js = tid >> 5;
    {
        const float* Xb = g_XT + (b * KK + js * 64) * DD + d4 * 4;
        ull ag[8][2];
#pragma unroll
        for (int i = 0; i < 8; i++) { ag[i][0] = 0ull; ag[i][1] = 0ull; }

#pragma unroll 8
        for (int t = 0; t < 64; t++) {
            float4 xq = *(const float4*)(Xb + t * DD);
            ull x01 = pk2(xq.x, xq.y), x23 = pk2(xq.z, xq.w);
            const int j = js * 64 + t;
#pragma unroll
            for (int i = 0; i < 8; i++) {
                ull a2 = bc2(se[i * KK + j]);
                ag[i][0] = ufma2(a2, x01, ag[i][0]);
                ag[i][1] = ufma2(a2, x23, ag[i][1]);
            }
        }
        // write partial results (reuse part as red[js][i][d])
        float* red = part;
#pragma unroll
        for (int i = 0; i < 8; i++) {
            float2 q0 = up2(ag[i][0]), q1 = up2(ag[i][1]);
            *(float4*)&red[js * 1024 + i * 128 + d4 * 4] =
                make_float4(q0.x, q0.y, q1.x, q1.y);
        }
    }
    __syncthreads();

    // ---- reduce over j-slices + sigmoid + residual ----
    {
        const float* red = part;
        const int i2 = tid >> 5;
        const int dq = (tid & 31) * 4;
        float4 s = make_float4(0.f, 0.f, 0.f, 0.f);
#pragma unroll
        for (int r = 0; r < 8; r++) {
            float4 p = *(const float4*)&red[r * 1024 + i2 * 128 + dq];
            s.x += p.x; s.y += p.y; s.z += p.z; s.w += p.w;
        }
        float4 xt = *(const float4*)&g_XT[(b * KK + i0 + i2) * DD + dq];
        out[(b * DD + dq + 0) * KK + i0 + i2] = 1.f / (1.f + __expf(-s.x)) + xt.x;
        out[(b * DD + dq + 1) * KK + i0 + i2] = 1.f / (1.f + __expf(-s.y)) + xt.y;
        out[(b * DD + dq + 2) * KK + i0 + i2] = 1.f / (1.f + __expf(-s.z)) + xt.z;
        out[(b * DD + dq + 3) * KK + i0 + i2] = 1.f / (1.f + __expf(-s.w)) + xt.w;
    }
}

extern "C" void kernel_launch(void* const* d_in, const int* in_sizes, int n_in,
                              void* d_out, int out_size) {
    const float* x    = (const float*)d_in[0];
    const float* lw   = (const float*)d_in[1];
    const float* lb   = (const float*)d_in[2];
    const float* a    = (const float*)d_in[3];
    const float* bias = (const float*)d_in[4];
    float* out = (float*)d_out;

    static bool attr_set = false;
    if (!attr_set) {
        cudaFuncSetAttribute(k2, cudaFuncAttributeMaxDynamicSharedMemorySize,
                             SM_FLTS * 4);
        attr_set = true;
    }
    k1<<<256, 256>>>(x, lw, lb, a);
    k2<<<256, 256, SM_FLTS * 4>>>(a, bias, out);
}

// round 7
// speedup vs baseline: 1.3466x; 1.0117x over previous
#include <cuda_runtime.h>

#define BB 4
#define DD 128
#define KK 512
// e = C1*(sL+sR) + C2*sum|t|a + bias, with alpha=0.2
#define C1 0.6f
#define C2 0.4f

typedef unsigned long long ull;
#define ABSM 0x7FFFFFFF7FFFFFFFULL

__device__ __forceinline__ ull uadd2(ull a, ull b) {
    ull r; asm("add.rn.f32x2 %0,%1,%2;" : "=l"(r) : "l"(a), "l"(b)); return r;
}
__device__ __forceinline__ ull ufma2(ull a, ull b, ull c) {
    ull r; asm("fma.rn.f32x2 %0,%1,%2,%3;" : "=l"(r) : "l"(a), "l"(b), "l"(c)); return r;
}
__device__ __forceinline__ ull bc2(float x) {
    ull r; asm("mov.b64 %0,{%1,%1};" : "=l"(r) : "f"(x)); return r;
}
__device__ __forceinline__ ull pk2(float x, float y) {
    ull r; asm("mov.b64 %0,{%1,%2};" : "=l"(r) : "f"(x), "f"(y)); return r;
}
__device__ __forceinline__ float2 up2(ull v) {
    float2 f; asm("mov.b64 {%0,%1},%2;" : "=f"(f.x), "=f"(f.y) : "l"(v)); return f;
}

__device__ float g_L[BB * KK * DD];   // [b][k][e]
__device__ float g_R[BB * DD * KK];   // [b][e][k]  (d-major)
__device__ float g_XT[BB * KK * DD];  // [b][k][d]
__device__ float g_sL[BB * KK];
__device__ float g_sR[BB * KK];

// ---------------- Kernel 1 ----------------
// thread = (k = tid&7, o8 = tid>>3): 8 outputs of ONE matrix, one k.
// Each lin_w element is read by exactly one 8-lane group per CTA (dedup'd LDG).
__global__ __launch_bounds__(256) void k1(const float* __restrict__ x,
                                          const float* __restrict__ lw,
                                          const float* __restrict__ lb,
                                          const float* __restrict__ a) {
    __shared__ float sx[128 * 9];  // [d][k] pad 9
    __shared__ float ssL[8], ssR[8];
    const int tid = threadIdx.x;
    const int b = blockIdx.x >> 6;
    const int k0 = (blockIdx.x & 63) << 3;

    for (int idx = tid; idx < 1024; idx += 256) {
        int d = idx >> 3, kk = idx & 7;
        sx[d * 9 + kk] = x[(b * DD + d) * KK + k0 + kk];
    }
    if (tid < 8) { ssL[tid] = 0.f; ssR[tid] = 0.f; }
    __syncthreads();

    const int k = tid & 7;
    const int o8 = tid >> 3;          // 0..31
    const int isL = (o8 < 16);        // warps 0-3: L, warps 4-7: R (no divergence)
    const int e0 = (o8 & 15) * 8;     // 8 outputs
    const float* Wb = lw + (isL ? 0 : 128 * 128) + e0;

    float acc[8] = {0, 0, 0, 0, 0, 0, 0, 0};
#pragma unroll 8
    for (int d = 0; d < 128; d++) {
        float xv = sx[d * 9 + k];
        float4 w0 = *(const float4*)(Wb + d * 128);
        float4 w1 = *(const float4*)(Wb + d * 128 + 4);
        acc[0] = fmaf(xv, w0.x, acc[0]); acc[1] = fmaf(xv, w0.y, acc[1]);
        acc[2] = fmaf(xv, w0.z, acc[2]); acc[3] = fmaf(xv, w0.w, acc[3]);
        acc[4] = fmaf(xv, w1.x, acc[4]); acc[5] = fmaf(xv, w1.y, acc[5]);
        acc[6] = fmaf(xv, w1.z, acc[6]); acc[7] = fmaf(xv, w1.w, acc[7]);
    }

    const float4 a0 = *(const float4*)&a[e0];
    const float4 a1 = *(const float4*)&a[e0 + 4];
    if (isL) {
        const float4 b0 = *(const float4*)&lb[e0];
        const float4 b1 = *(const float4*)&lb[e0 + 4];
        acc[0] += b0.x; acc[1] += b0.y; acc[2] += b0.z; acc[3] += b0.w;
        acc[4] += b1.x; acc[5] += b1.y; acc[6] += b1.z; acc[7] += b1.w;
        *(float4*)&g_L[(b * KK + k0 + k) * DD + e0] =
            make_float4(acc[0], acc[1], acc[2], acc[3]);
        *(float4*)&g_L[(b * KK + k0 + k) * DD + e0 + 4] =
            make_float4(acc[4], acc[5], acc[6], acc[7]);
    } else {
#pragma unroll
        for (int q = 0; q < 8; q++)
            g_R[(b * DD + e0 + q) * KK + k0 + k] = acc[q];
    }

    float p = acc[0] * a0.x + acc[1] * a0.y + acc[2] * a0.z + acc[3] * a0.w +
              acc[4] * a1.x + acc[5] * a1.y + acc[6] * a1.z + acc[7] * a1.w;
    atomicAdd(isL ? &ssL[k] : &ssR[k], p);
    __syncthreads();

    for (int idx = tid; idx < 1024; idx += 256) {
        int kk = idx >> 7, d = idx & 127;
        g_XT[(b * KK + k0 + kk) * DD + d] = sx[d * 9 + kk];
    }
    if (tid < 8) {
        g_sL[b * KK + k0 + tid] = ssL[tid];
        g_sR[b * KK + k0 + tid] = ssR[tid];
    }
}

// ---------------- Kernel 2 ----------------
// smem floats: sLd[128][8] dup @0 (2048) | sAd[128] dup @2048 (256)
//   part[2][8][512] @2304 (8192) | se[8][512] @10496 (4096) | seD @14592 (10240)
#define OF_SAD  2048
#define OF_PART 2304
#define OF_SE   10496
#define OF_SED  14592
#define SM_FLTS 24832
#define SED_P   10  // ull pitch per j row

__global__ __launch_bounds__(256, 2) void k2(const float* __restrict__ a,
                                             const float* __restrict__ bias,
                                             float* __restrict__ out) {
    extern __shared__ float sm[];
    ull*   sLd  = (ull*)sm;            // [d][i] dup pairs
    ull*   sAd  = (ull*)(sm + OF_SAD); // [d] dup pairs
    float* part = sm + OF_PART;        // [sp][i][j]
    float* se   = sm + OF_SE;          // [i][j]
    ull*   seD  = (ull*)(sm + OF_SED); // [j][i] dup pairs, pitch 10
    __shared__ float sSL[8];

    const int tid = threadIdx.x;
    const int b = blockIdx.x >> 6;
    const int i0 = (blockIdx.x & 63) << 3;

    for (int idx = tid; idx < 1024; idx += 256) {
        int d = idx >> 3, i = idx & 7;
        sLd[idx] = bc2(g_L[(b * KK + i0 + i) * DD + d]);
    }
    if (tid < 128) sAd[tid] = bc2(a[tid]);
    if (tid < 8) sSL[tid] = g_sL[b * KK + i0 + tid];
    __syncthreads();

    // ---- e phase: split-d (sp), thread = 4 j (2 packed j-pairs) x 8 i ----
    {
        const int jq = tid & 127;
        const int sp = tid >> 7;
        const float* Rb = g_R + (b * DD + sp * 64) * KK + jq * 4;
        const ull* sLdsp = sLd + sp * 64 * 8;
        const ull* sAdsp = sAd + sp * 64;
        ull acc[8][2];
#pragma unroll
        for (int i = 0; i < 8; i++) { acc[i][0] = 0ull; acc[i][1] = 0ull; }

#pragma unroll 8
        for (int dd = 0; dd < 64; dd++) {
            float4 rq = *(const float4*)(Rb + dd * KK);
            ull r01 = pk2(rq.x, rq.y), r23 = pk2(rq.z, rq.w);
            ull av2 = sAdsp[dd];
#pragma unroll
            for (int ip = 0; ip < 4; ip++) {
                ulonglong2 lp = *(const ulonglong2*)&sLdsp[dd * 8 + ip * 2];
                ull u0 = uadd2(lp.x, r01) & ABSM;
                ull u1 = uadd2(lp.x, r23) & ABSM;
                acc[2 * ip][0] = ufma2(u0, av2, acc[2 * ip][0]);
                acc[2 * ip][1] = ufma2(u1, av2, acc[2 * ip][1]);
                ull v0 = uadd2(lp.y, r01) & ABSM;
                ull v1 = uadd2(lp.y, r23) & ABSM;
                acc[2 * ip + 1][0] = ufma2(v0, av2, acc[2 * ip + 1][0]);
                acc[2 * ip + 1][1] = ufma2(v1, av2, acc[2 * ip + 1][1]);
            }
        }
        float* pp = part + sp * 4096 + jq * 4;
#pragma unroll
        for (int i = 0; i < 8; i++) {
            float2 q0 = up2(acc[i][0]), q1 = up2(acc[i][1]);
            *(float4*)&pp[i * KK] = make_float4(q0.x, q0.y, q1.x, q1.y);
        }
    }
    __syncthreads();

    // ---- combine: e = C1*(sL+sR) + C2*(p0+p1) + bias -> se[i][j] ----
    {
        const int jq2 = tid & 127;
        const int ih0 = (tid >> 7) * 4;
        float4 sr = *(const float4*)&g_sR[b * KK + jq2 * 4];
#pragma unroll
        for (int r = 0; r < 4; r++) {
            int i = ih0 + r;
            float4 p0 = *(const float4*)&part[i * KK + jq2 * 4];
            float4 p1 = *(const float4*)&part[4096 + i * KK + jq2 * 4];
            float4 bz = *(const float4*)&bias[(long)(i0 + i) * KK + jq2 * 4];
            float sl = sSL[i];
            float4 ev;
            ev.x = C1 * (sl + sr.x) + C2 * (p0.x + p1.x) + bz.x;
            ev.y = C1 * (sl + sr.y) + C2 * (p0.y + p1.y) + bz.y;
            ev.z = C1 * (sl + sr.z) + C2 * (p0.z + p1.z) + bz.z;
            ev.w = C1 * (sl + sr.w) + C2 * (p0.w + p1.w) + bz.w;
            *(float4*)&se[i * KK + jq2 * 4] = ev;
        }
    }
    __syncthreads();

    // ---- softmax: warp w -> row i=w; write duplicated transpose seD[j][i] ----
    {
        const int w = tid >> 5, lane = tid & 31;
        const float* row = se + w * KK;
        float v[16], m = -3.4e38f;
#pragma unroll
        for (int t = 0; t < 16; t++) { v[t] = row[t * 32 + lane]; m = fmaxf(m, v[t]); }
#pragma unroll
        for (int o = 16; o > 0; o >>= 1) m = fmaxf(m, __shfl_xor_sync(0xffffffffu, m, o));
        float s = 0.f;
#pragma unroll
        for (int t = 0; t < 16; t++) { v[t] = __expf(v[t] - m); s += v[t]; }
#pragma unroll
        for (int o = 16; o > 0; o >>= 1) s += __shfl_xor_sync(0xffffffffu, s, o);
        float inv = 1.f / s;
#pragma unroll
        for (int t = 0; t < 16; t++)
            seD[(t * 32 + lane) * SED_P + w] = bc2(v[t] * inv);
    }
    __syncthreads();

    // ---- agg: attn @ XT, thread = (j-slice, d-quad), d packed in pairs ----
    const int d4 = tid & 31;
    const int js = tid >> 5;
    {
        const float* Xb = g_XT + (b * KK + js * 64) * DD + d4 * 4;
        ull ag[8][2];
#pragma unroll
        for (int i = 0; i < 8; i++) { ag[i][0] = 0ull; ag[i][1] = 0ull; }

#pragma unroll 8
        for (int t = 0; t < 64; t++) {
            float4 xq = *(const float4*)(Xb + t * DD);
            ull x01 = pk2(xq.x, xq.y), x23 = pk2(xq.z, xq.w);
            const ull* sd = seD + (js * 64 + t) * SED_P;
#pragma unroll
            for (int ip = 0; ip < 4; ip++) {
                ulonglong2 ap = *(const ulonglong2*)&sd[ip * 2];
                ag[2 * ip][0] = ufma2(ap.x, x01, ag[2 * ip][0]);
                ag[2 * ip][1] = ufma2(ap.x, x23, ag[2 * ip][1]);
                ag[2 * ip + 1][0] = ufma2(ap.y, x01, ag[2 * ip + 1][0]);
                ag[2 * ip + 1][1] = ufma2(ap.y, x23, ag[2 * ip + 1][1]);
            }
        }
        float* red = part;  // reuse: [js][i][d]
#pragma unroll
        for (int i = 0; i < 8; i++) {
            float2 q0 = up2(ag[i][0]), q1 = up2(ag[i][1]);
            *(float4*)&red[js * 1024 + i * 128 + d4 * 4] =
                make_float4(q0.x, q0.y, q1.x, q1.y);
        }
    }
    __syncthreads();

    // ---- reduce over j-slices + sigmoid + residual ----
    {
        const float* red = part;
        const int i2 = tid >> 5;
        const int dq = (tid & 31) * 4;
        float4 s = make_float4(0.f, 0.f, 0.f, 0.f);
#pragma unroll
        for (int r = 0; r < 8; r++) {
            float4 p = *(const float4*)&red[r * 1024 + i2 * 128 + dq];
            s.x += p.x; s.y += p.y; s.z += p.z; s.w += p.w;
        }
        float4 xt = *(const float4*)&g_XT[(b * KK + i0 + i2) * DD + dq];
        out[(b * DD + dq + 0) * KK + i0 + i2] = 1.f / (1.f + __expf(-s.x)) + xt.x;
        out[(b * DD + dq + 1) * KK + i0 + i2] = 1.f / (1.f + __expf(-s.y)) + xt.y;
        out[(b * DD + dq + 2) * KK + i0 + i2] = 1.f / (1.f + __expf(-s.z)) + xt.z;
        out[(b * DD + dq + 3) * KK + i0 + i2] = 1.f / (1.f + __expf(-s.w)) + xt.w;
    }
}

extern "C" void kernel_launch(void* const* d_in, const int* in_sizes, int n_in,
                              void* d_out, int out_size) {
    const float* x    = (const float*)d_in[0];
    const float* lw   = (const float*)d_in[1];
    const float* lb   = (const float*)d_in[2];
    const float* a    = (const float*)d_in[3];
    const float* bias = (const float*)d_in[4];
    float* out = (float*)d_out;

    static bool attr_set = false;
    if (!attr_set) {
        cudaFuncSetAttribute(k2, cudaFuncAttributeMaxDynamicSharedMemorySize,
                             SM_FLTS * 4);
        attr_set = true;
    }
    k1<<<256, 256>>>(x, lw, lb, a);
    k2<<<256, 256, SM_FLTS * 4>>>(a, bias, out);
}